// round 1
// baseline (speedup 1.0000x reference)
#include <cuda_runtime.h>
#include <math.h>

// ---------------- problem constants ----------------
#define BB     32
#define NENT   1024
#define LQL    128
#define DFEAT  2112
#define CTX    512
#define CMD    512
#define TT     4
#define MROWS  (BB*NENT)     // 32768
#define NEGV   (-1e30f)

// ---------------- scratch (device globals; no allocation allowed) ----------------
__device__ float g_invnorm[MROWS];
__device__ float g_xloc   [(size_t)MROWS*CTX];
__device__ float g_xctx0  [(size_t)MROWS*CTX];
__device__ float g_xctx1  [(size_t)MROWS*CTX];
__device__ float g_projloc[(size_t)MROWS*CTX];
__device__ float g_pp     [(size_t)MROWS*CTX];
__device__ float g_q      [(size_t)MROWS*CTX];
__device__ float g_k      [(size_t)MROWS*CTX];
__device__ float g_v      [(size_t)MROWS*CTX];
__device__ float g_msg    [(size_t)MROWS*CTX];
__device__ float g_score  [(size_t)BB*NENT*NENT];
__device__ float g_qbase  [BB*CMD];
__device__ float g_qcmd   [BB*CMD];
__device__ float g_cmd    [BB*CMD];
__device__ float g_pkg    [BB*CTX];
__device__ float g_pvg    [BB*CTX];

// ---------------- generic tiled SGEMM ----------------
// C[M,N] = epilogue( A @ B ),  A row-major (optionally a virtual concat of up
// to 3 buffers each 512 cols wide), B row-major [K,N] or (TB) row-major [N,K].
// Tile 128x128x8, 256 threads, 8x8 per thread. All dims are exact multiples.
#define BM 128
#define BN 128
#define BK 8
#define TM 8
#define TN 8
#define SPAD 4

// EPI: 0: out = acc*alpha + bias[n]
//      1: out = acc*extra[m] + bias[n]                      (row scale: initKB)
//      2: out = (acc + bias[n]) * extra[(m>>10)*ldgate + n] (per-batch gate: k,v)
//      3: out = (acc + bias[n]) * extra[m*ldc + n]          (elementwise: pp)
template<int NSRC, bool TB, int EPI>
__global__ __launch_bounds__(256, 2)
void gemm_kernel(const float* __restrict__ A0, const float* __restrict__ A1,
                 const float* __restrict__ A2, const float* __restrict__ Bm,
                 const float* __restrict__ bias, const float* __restrict__ extra,
                 float* __restrict__ C,
                 int K, int lda, int ldb, int ldc, int ldgate,
                 size_t sA, size_t sB, size_t sC, float alpha)
{
    __shared__ float As[BK][BM + SPAD];
    __shared__ float Bs[BK][BN + SPAD];

    const int z = blockIdx.z;
    const float* Abase = A0 + (size_t)z * sA;
    const float* Bbase = Bm + (size_t)z * sB;
    float* Cbase = C + (size_t)z * sC;

    const int m0 = blockIdx.y * BM;
    const int n0 = blockIdx.x * BN;
    const int tid = threadIdx.x;

    const int ldRow = tid >> 1;          // 0..127
    const int ldCol = (tid & 1) * 4;     // 0 or 4
    const int bRow  = tid >> 5;          // 0..7
    const int bCol  = (tid & 31) * 4;    // 0..124

    const int tx = tid & 15;
    const int ty = tid >> 4;

    float acc[TM][TN] = {};

    for (int k0 = 0; k0 < K; k0 += BK) {
        // ---- load A tile (transposed into smem) ----
        const float* Ap; int ac; int al;
        if (NSRC == 1) { Ap = Abase; ac = k0; al = lda; }
        else {
            const int src = k0 >> 9;     // 512-wide chunks
            Ap = (src == 0) ? A0 : ((src == 1) ? A1 : A2);
            ac = k0 & 511; al = 512;
        }
        float4 av = *reinterpret_cast<const float4*>(Ap + (size_t)(m0 + ldRow) * al + ac + ldCol);
        As[ldCol + 0][ldRow] = av.x;
        As[ldCol + 1][ldRow] = av.y;
        As[ldCol + 2][ldRow] = av.z;
        As[ldCol + 3][ldRow] = av.w;

        // ---- load B tile ----
        if (!TB) {
            float4 bv = *reinterpret_cast<const float4*>(Bbase + (size_t)(k0 + bRow) * ldb + n0 + bCol);
            *reinterpret_cast<float4*>(&Bs[bRow][bCol]) = bv;
        } else {
            float4 bv = *reinterpret_cast<const float4*>(Bbase + (size_t)(n0 + ldRow) * ldb + k0 + ldCol);
            Bs[ldCol + 0][ldRow] = bv.x;
            Bs[ldCol + 1][ldRow] = bv.y;
            Bs[ldCol + 2][ldRow] = bv.z;
            Bs[ldCol + 3][ldRow] = bv.w;
        }
        __syncthreads();

        #pragma unroll
        for (int kk = 0; kk < BK; kk++) {
            float ar[TM], br[TN];
            #pragma unroll
            for (int i = 0; i < TM; i++) ar[i] = As[kk][ty * TM + i];
            #pragma unroll
            for (int j = 0; j < TN; j++) br[j] = Bs[kk][tx * TN + j];
            #pragma unroll
            for (int i = 0; i < TM; i++)
                #pragma unroll
                for (int j = 0; j < TN; j++)
                    acc[i][j] = fmaf(ar[i], br[j], acc[i][j]);
        }
        __syncthreads();
    }

    // ---- epilogue ----
    float bcol[TN];
    #pragma unroll
    for (int j = 0; j < TN; j++) bcol[j] = bias ? bias[n0 + tx * TN + j] : 0.f;

    #pragma unroll
    for (int i = 0; i < TM; i++) {
        const int m = m0 + ty * TM + i;
        float out[TN];
        if (EPI == 0) {
            #pragma unroll
            for (int j = 0; j < TN; j++) out[j] = acc[i][j] * alpha + bcol[j];
        } else if (EPI == 1) {
            const float rs = extra[m];
            #pragma unroll
            for (int j = 0; j < TN; j++) out[j] = acc[i][j] * rs + bcol[j];
        } else if (EPI == 2) {
            const float* g = extra + (size_t)(m >> 10) * ldgate + n0 + tx * TN;
            #pragma unroll
            for (int j = 0; j < TN; j++) out[j] = (acc[i][j] + bcol[j]) * g[j];
        } else { // EPI == 3
            const float* g = extra + (size_t)m * ldc + n0 + tx * TN;
            #pragma unroll
            for (int j = 0; j < TN; j++) out[j] = (acc[i][j] + bcol[j]) * g[j];
        }
        float4* cp = reinterpret_cast<float4*>(Cbase + (size_t)m * ldc + n0 + tx * TN);
        cp[0] = make_float4(out[0], out[1], out[2], out[3]);
        cp[1] = make_float4(out[4], out[5], out[6], out[7]);
    }
}

// ---------------- small helper kernels ----------------

// inverse L2 norm of each image row (folded into initKB epilogue)
__global__ void rownorm_kernel(const float* __restrict__ img, float* __restrict__ invn)
{
    const int m = blockIdx.x;
    const float* r = img + (size_t)m * DFEAT;
    const int tid = threadIdx.x;
    float s = 0.f;
    for (int k = tid; k < DFEAT; k += 256) { float x = r[k]; s = fmaf(x, x, s); }
    __shared__ float red[256];
    red[tid] = s; __syncthreads();
    for (int o = 128; o > 0; o >>= 1) { if (tid < o) red[tid] += red[tid + o]; __syncthreads(); }
    if (tid == 0) invn[m] = 1.f / fmaxf(sqrtf(red[0]), 1e-12f);
}

__global__ void ctx_init_kernel(const float* __restrict__ initMem, float* __restrict__ xctx)
{
    const size_t i = (size_t)blockIdx.x * blockDim.x + threadIdx.x;
    xctx[i] = initMem[i & (CTX - 1)];
}

// [32,512] = in[32,512] @ W[512,512] + b  (optional ELU)
template<bool ELU>
__global__ void small_linear_kernel(const float* __restrict__ in, const float* __restrict__ W,
                                    const float* __restrict__ bias, float* __restrict__ out)
{
    const int b = blockIdx.x;
    const int tid = threadIdx.x;
    __shared__ float x[CMD];
    for (int d = tid; d < CMD; d += 256) x[d] = in[b * CMD + d];
    __syncthreads();
    for (int j = tid; j < CMD; j += 256) {
        float acc = 0.f;
        #pragma unroll 4
        for (int k = 0; k < CMD; k++) acc = fmaf(x[k], W[(size_t)k * CMD + j], acc);
        acc += bias[j];
        if (ELU) acc = (acc > 0.f) ? acc : expm1f(acc);
        out[b * CMD + j] = acc;
    }
}

// textual command: raw = (q_cmd * lstm) @ c2l_w + c2l_b ; masked softmax ; cmd = att @ lstm
__global__ void text_cmd_kernel(const float* __restrict__ qcmd, const float* __restrict__ lstm,
                                const float* __restrict__ c2l_w, const float* __restrict__ c2l_b,
                                const int* __restrict__ qlen, float* __restrict__ cmd)
{
    const int b = blockIdx.x;
    const int tid = threadIdx.x;
    __shared__ float e[CMD];
    __shared__ float att[LQL];
    for (int d = tid; d < CMD; d += 256) e[d] = qcmd[b * CMD + d] * c2l_w[d];
    __syncthreads();
    if (tid < LQL) {
        const float* L = lstm + ((size_t)b * LQL + tid) * CMD;
        float acc = 0.f;
        for (int d = 0; d < CMD; d++) acc = fmaf(L[d], e[d], acc);
        acc += c2l_b[0];
        att[tid] = (tid >= qlen[b]) ? NEGV : acc;
    }
    __syncthreads();
    if (tid == 0) {
        float mx = -3.4e38f;
        for (int l = 0; l < LQL; l++) mx = fmaxf(mx, att[l]);
        float sum = 0.f;
        for (int l = 0; l < LQL; l++) { att[l] = expf(att[l] - mx); sum += att[l]; }
        const float inv = 1.f / sum;
        for (int l = 0; l < LQL; l++) att[l] *= inv;
    }
    __syncthreads();
    for (int d = tid; d < CMD; d += 256) {
        float acc = 0.f;
        #pragma unroll 4
        for (int l = 0; l < LQL; l++) acc = fmaf(att[l], lstm[((size_t)b * LQL + l) * CMD + d], acc);
        cmd[b * CMD + d] = acc;
    }
}

// masked row softmax over the [B,N,N] score tensor (in place)
__global__ void attn_softmax_kernel(float* __restrict__ score, const int* __restrict__ entity_num)
{
    const int row = blockIdx.x;        // 0 .. B*N-1
    const int b = row >> 10;
    const int n = row & 1023;
    const int en = entity_num[b];
    float* s = score + (size_t)row * NENT;
    const bool rmask = (n >= en);
    const int tid = threadIdx.x;

    float v[4];
    float mx = -3.4e38f;
    #pragma unroll
    for (int j = 0; j < 4; j++) {
        const int m = tid + j * 256;
        float x = s[m];
        x = (rmask || m >= en) ? NEGV : x;
        v[j] = x;
        mx = fmaxf(mx, x);
    }
    __shared__ float red[256];
    red[tid] = mx; __syncthreads();
    for (int o = 128; o > 0; o >>= 1) { if (tid < o) red[tid] = fmaxf(red[tid], red[tid + o]); __syncthreads(); }
    mx = red[0];
    __syncthreads();

    float sum = 0.f;
    #pragma unroll
    for (int j = 0; j < 4; j++) { v[j] = expf(v[j] - mx); sum += v[j]; }
    red[tid] = sum; __syncthreads();
    for (int o = 128; o > 0; o >>= 1) { if (tid < o) red[tid] += red[tid + o]; __syncthreads(); }
    const float inv = 1.f / red[0];

    #pragma unroll
    for (int j = 0; j < 4; j++) s[tid + j * 256] = v[j] * inv;
}

// ---------------- launch ----------------
template<typename T> static float* symaddr(T& sym) {
    void* p = nullptr;
    cudaGetSymbolAddress(&p, sym);
    return (float*)p;
}

extern "C" void kernel_launch(void* const* d_in, const int* in_sizes, int n_in,
                              void* d_out, int out_size)
{
    const float* images    = (const float*)d_in[0];
    const float* q_enc     = (const float*)d_in[1];
    const float* lstm      = (const float*)d_in[2];
    const int*   q_length  = (const int*)  d_in[3];
    const int*   ent_num   = (const int*)  d_in[4];
    const float* initKB_w  = (const float*)d_in[5];
    const float* initKB_b  = (const float*)d_in[6];
    const float* initMem   = (const float*)d_in[7];
    const float* qInput_w  = (const float*)d_in[8];
    const float* qInput_b  = (const float*)d_in[9];
    const float* qInput2_w = (const float*)d_in[10];
    const float* qInput2_b = (const float*)d_in[11];
    const float* c2l_w     = (const float*)d_in[12];
    const float* c2l_b     = (const float*)d_in[13];
    const float* pxl_w     = (const float*)d_in[14];
    const float* pxl_b     = (const float*)d_in[15];
    const float* pxc_w     = (const float*)d_in[16];
    const float* pxc_b     = (const float*)d_in[17];
    const float* qry_w     = (const float*)d_in[18];
    const float* qry_b     = (const float*)d_in[19];
    const float* key_w     = (const float*)d_in[20];
    const float* key_b     = (const float*)d_in[21];
    const float* val_w     = (const float*)d_in[22];
    const float* val_b     = (const float*)d_in[23];
    const float* pk_w      = (const float*)d_in[24];
    const float* pk_b      = (const float*)d_in[25];
    const float* pv_w      = (const float*)d_in[26];
    const float* pv_b      = (const float*)d_in[27];
    const float* mu_w      = (const float*)d_in[28];
    const float* mu_b      = (const float*)d_in[29];
    const float* ck_w      = (const float*)d_in[30];
    const float* ck_b      = (const float*)d_in[31];

    float* invn    = symaddr(g_invnorm);
    float* xloc    = symaddr(g_xloc);
    float* xctx[2] = { symaddr(g_xctx0), symaddr(g_xctx1) };
    float* projloc = symaddr(g_projloc);
    float* pp      = symaddr(g_pp);
    float* q       = symaddr(g_q);
    float* k       = symaddr(g_k);
    float* v       = symaddr(g_v);
    float* msg     = symaddr(g_msg);
    float* score   = symaddr(g_score);
    float* qbase   = symaddr(g_qbase);
    float* qcmd    = symaddr(g_qcmd);
    float* cmd     = symaddr(g_cmd);
    float* pkg     = symaddr(g_pkg);
    float* pvg     = symaddr(g_pvg);

    const float scale = 0.044194173824159216f;   // 1/sqrt(512)
    const dim3 gridMain(CTX / BN, MROWS / BM, 1);          // (4, 256)
    const dim3 gridScore(NENT / BN, NENT / BM, BB);        // (8, 8, 32)
    const dim3 gridMsg(CTX / BN, NENT / BM, BB);           // (4, 8, 32)

    // ---- setup ----
    rownorm_kernel<<<MROWS, 256>>>(images, invn);
    ctx_init_kernel<<<(MROWS * CTX) / 256, 256>>>(initMem, xctx[0]);
    small_linear_kernel<true><<<BB, 256>>>(q_enc, qInput_w, qInput_b, qbase);

    // x_loc = normalize(images) @ initKB_w + b    (norm folded into epilogue)
    gemm_kernel<1, false, 1><<<gridMain, 256>>>(
        images, nullptr, nullptr, initKB_w, initKB_b, invn, xloc,
        DFEAT, DFEAT, CTX, CTX, 0, 0, 0, 0, 1.f);

    int cur = 0;
    for (int t = 0; t < TT; t++) {
        // textual command
        small_linear_kernel<false><<<BB, 256>>>(qbase, qInput2_w + (size_t)t * CMD * CMD,
                                                qInput2_b + (size_t)t * CMD, qcmd);
        text_cmd_kernel<<<BB, 256>>>(qcmd, lstm, c2l_w, c2l_b, q_length, cmd);
        small_linear_kernel<false><<<BB, 256>>>(cmd, pk_w, pk_b, pkg);
        small_linear_kernel<false><<<BB, 256>>>(cmd, pv_w, pv_b, pvg);

        // proj_loc = x_loc @ pxl + b
        gemm_kernel<1, false, 0><<<gridMain, 256>>>(
            xloc, nullptr, nullptr, pxl_w, pxl_b, nullptr, projloc,
            CTX, CTX, CTX, CTX, 0, 0, 0, 0, 1.f);
        // pp = (x_ctx @ pxc + b) * proj_loc
        gemm_kernel<1, false, 3><<<gridMain, 256>>>(
            xctx[cur], nullptr, nullptr, pxc_w, pxc_b, projloc, pp,
            CTX, CTX, CTX, CTX, 0, 0, 0, 0, 1.f);

        // q/k/v over virtual concat [x_loc | x_ctx | pp]  (K = 1536)
        gemm_kernel<3, false, 0><<<gridMain, 256>>>(
            xloc, xctx[cur], pp, qry_w, qry_b, nullptr, q,
            3 * CTX, 0, CTX, CTX, 0, 0, 0, 0, 1.f);
        gemm_kernel<3, false, 2><<<gridMain, 256>>>(
            xloc, xctx[cur], pp, key_w, key_b, pkg, k,
            3 * CTX, 0, CTX, CTX, CTX, 0, 0, 0, 1.f);
        gemm_kernel<3, false, 2><<<gridMain, 256>>>(
            xloc, xctx[cur], pp, val_w, val_b, pvg, v,
            3 * CTX, 0, CTX, CTX, CTX, 0, 0, 0, 1.f);

        // score[b] = scale * q[b] @ k[b]^T   (batched NT)
        gemm_kernel<1, true, 0><<<gridScore, 256>>>(
            q, nullptr, nullptr, k, nullptr, nullptr, score,
            CTX, CTX, CTX, NENT, 0,
            (size_t)NENT * CTX, (size_t)NENT * CTX, (size_t)NENT * NENT, scale);

        attn_softmax_kernel<<<MROWS, 256>>>(score, ent_num);

        // message[b] = prob[b] @ v[b]   (batched NN)
        gemm_kernel<1, false, 0><<<gridMsg, 256>>>(
            score, nullptr, nullptr, v, nullptr, nullptr, msg,
            NENT, NENT, CTX, CTX, 0,
            (size_t)NENT * NENT, (size_t)NENT * CTX, (size_t)NENT * CTX, 1.f);

        // x_ctx' = [x_ctx | message] @ mu + b
        gemm_kernel<2, false, 0><<<gridMain, 256>>>(
            xctx[cur], msg, nullptr, mu_w, mu_b, nullptr, xctx[cur ^ 1],
            2 * CTX, 0, CTX, CTX, 0, 0, 0, 0, 1.f);
        cur ^= 1;
    }

    // out = [x_loc | x_ctx] @ ck + b
    gemm_kernel<2, false, 0><<<gridMain, 256>>>(
        xloc, xctx[cur], nullptr, ck_w, ck_b, nullptr, (float*)d_out,
        2 * CTX, 0, CTX, CTX, 0, 0, 0, 0, 1.f);
}